// round 2
// baseline (speedup 1.0000x reference)
#include <cuda_runtime.h>
#include <cuda_bf16.h>

// Problem constants
#define NB   16
#define NIN  256
#define NOUT 512
#define NPHI 256
#define NT   240
#define KH   131584            // 512 * 257 (Hermitian half over axis -1)
#define KSPLIT 8
#define KPB  (KH / KSPLIT)     // 16448
#define KC   16
#define BM   64
#define BP   (NB * NPHI)       // 4096

// ---------------- device scratch (static; no allocation) ----------------
__device__ float2  g_W[NB * NOUT * NOUT];          // full spectrum, 33.5 MB
__device__ float   g_G[(size_t)KH * NT];           // 126 MB
__device__ unsigned g_ab[KH];
__device__ float   g_Part[(size_t)KSPLIT * BP * NT]; // 31.5 MB

// ---------------- 512-point radix-2 DIT FFT in shared memory ----------------
// sign = -1 -> forward DFT (matches numpy/jax fftn). Input loaded bit-reversed,
// output in natural order.
__device__ __forceinline__ void fft512(float2* buf, int tid, float sign)
{
    #pragma unroll
    for (int s = 0; s < 9; s++) {
        int half = 1 << s;
        int pos  = tid & (half - 1);
        int i0   = ((tid >> s) << (s + 1)) + pos;
        int i1   = i0 + half;
        float ang = sign * 3.14159265358979323846f * (float)pos / (float)half;
        float sv, cv;
        sincosf(ang, &sv, &cv);           // NOTE: sin first, cos second
        __syncthreads();
        float2 x0 = buf[i0];
        float2 x1 = buf[i1];
        float tr = x1.x * cv - x1.y * sv; // x1 * e^{i*ang}
        float ti = x1.x * sv + x1.y * cv;
        buf[i0] = make_float2(x0.x + tr, x0.y + ti);
        buf[i1] = make_float2(x0.x - tr, x0.y - ti);
    }
    __syncthreads();
}

// Row FFTs of the zero-padded input: f [16,1,256,256] -> g_W rows
__global__ void fft_rows_kernel(const float* __restrict__ f)
{
    int a  = blockIdx.x;   // output row 0..511 (axis -2 index)
    int bb = blockIdx.y;   // batch
    int tid = threadIdx.x; // 0..255
    float2* wrow = g_W + ((size_t)bb << 18) + ((size_t)a << 9);

    if (a < 128 || a >= 384) {
        for (int i = tid; i < 512; i += 256) wrow[i] = make_float2(0.f, 0.f);
        return;
    }
    __shared__ float2 buf[512];
    const float* frow = f + (size_t)bb * (NIN * NIN) + (size_t)(a - 128) * NIN;
    for (int i = tid; i < 512; i += 256) {
        float v = (i >= 128 && i < 384) ? frow[i - 128] : 0.f;
        buf[__brev((unsigned)i) >> 23] = make_float2(v, 0.f);
    }
    fft512(buf, tid, -1.0f);
    for (int i = tid; i < 512; i += 256) wrow[i] = buf[i];
}

// Column FFTs, in place
__global__ void fft_cols_kernel()
{
    int c  = blockIdx.x;   // column (axis -1 index)
    int bb = blockIdx.y;
    int tid = threadIdx.x;
    float2* base = g_W + ((size_t)bb << 18) + c;
    __shared__ float2 buf[512];
    for (int i = tid; i < 512; i += 256)
        buf[__brev((unsigned)i) >> 23] = base[(size_t)i << 9];
    fft512(buf, tid, -1.0f);
    for (int i = tid; i < 512; i += 256) base[(size_t)i << 9] = buf[i];
}

// G[kh][t] = g_{t+1}(k) * weight / N^2, plus (a,b) table.
// kh = a*257 + b, a in [0,512), b in [0,257)  (half spectrum over axis -1)
__global__ void ggen_kernel(const float* __restrict__ fil)
{
    int kh = blockIdx.x * 256 + threadIdx.x;
    if (kh >= KH) return;
    unsigned a = (unsigned)kh / 257u;
    unsigned b = (unsigned)kh - a * 257u;
    float c2 = 2.0f - 4.0f * fil[a * 512u + b];
    float w  = (b == 0u || b == 256u) ? 1.0f : 2.0f;
    float scale = w * (1.0f / 262144.0f);
    g_ab[kh] = (a << 9) | b;
    float gp = scale;                // g_0 * scale
    float gc = (c2 - 1.0f) * scale;  // g_1 * scale
    float* go = g_G + (size_t)kh * NT;
    #pragma unroll 8
    for (int t = 0; t < NT; t++) {
        go[t] = gc;
        float gn = c2 * gc - gp;
        gp = gc; gc = gn;
    }
}

// packed fp32x2 helpers
__device__ __forceinline__ unsigned long long pack2(float x, float y)
{
    unsigned long long r;
    asm("mov.b64 %0, {%1,%2};" : "=l"(r) : "f"(x), "f"(y));
    return r;
}
__device__ __forceinline__ void ffma2(unsigned long long& d,
                                      unsigned long long a,
                                      unsigned long long b)
{
    asm("fma.rn.f32x2 %0, %1, %2, %0;" : "+l"(d) : "l"(a), "l"(b));
}

// GEMM: Part[ks][bp][t] = sum_{k in split ks} m(bp,k) * G[k][t]
// m(bp,k) = ReW0[b][k]*cos(phi) - ImW0[b][k]*sin(phi),
// phi = 2*pi*((a*idx0[p] + b*idx1[p]) mod 512)/512
__global__ void __launch_bounds__(192, 2)
gemm_kernel(const int* __restrict__ idx0, const int* __restrict__ idx1)
{
    __shared__ float ct[512], st[512];
    __shared__ int   px[BM], py[BM];
    __shared__ float sG[KC * NT];
    __shared__ float sm[KC][BM];
    __shared__ unsigned sv[KC];
    __shared__ float2   sw[KC];

    const int tid = threadIdx.x;          // 0..191
    const int bx  = blockIdx.x;           // 0..63  -> bp tile
    const int ks  = blockIdx.y;           // 0..7   -> k split
    const int bb  = bx >> 2;              // batch (4 tiles of 64 p per batch)
    const int p0  = (bx & 3) * BM;

    for (int i = tid; i < 512; i += 192) {
        float sv_, cv_;
        sincosf(6.283185307179586477f * (float)i * (1.0f / 512.0f), &sv_, &cv_);
        ct[i] = cv_; st[i] = sv_;          // NOTE: sin first, cos second
    }
    for (int i = tid; i < BM; i += 192) { px[i] = idx0[p0 + i]; py[i] = idx1[p0 + i]; }

    // thread tile: 4 rows x 20 t (10 packed pairs)
    const int tg = tid % 12;
    const int rq = tid / 12;      // 0..15
    const int r0 = rq * 4;
    const int t0 = tg * 20;

    unsigned long long acc[4][10];
    #pragma unroll
    for (int i = 0; i < 4; i++)
        #pragma unroll
        for (int j = 0; j < 10; j++) acc[i][j] = 0ull;

    const float2* Wb = g_W + ((size_t)bb << 18);
    const int kbase = ks * KPB;

    for (int kc = 0; kc < KPB; kc += KC) {
        __syncthreads();
        if (tid < KC) {
            unsigned v = g_ab[kbase + kc + tid];
            sv[tid] = v;
            sw[tid] = Wb[v];   // v = (a<<9)|b = a*512+b : direct spectrum offset
        }
        const float* Gsrc = g_G + (size_t)(kbase + kc) * NT;
        for (int i = tid; i < KC * NT; i += 192) sG[i] = Gsrc[i];
        __syncthreads();

        for (int i = tid; i < KC * BM; i += 192) {
            int r = i & (BM - 1);
            int kk = i >> 6;
            unsigned v = sv[kk];
            unsigned ph = ((v >> 9) * (unsigned)px[r] + (v & 511u) * (unsigned)py[r]) & 511u;
            float2 w = sw[kk];
            sm[kk][r] = w.x * ct[ph] - w.y * st[ph];
        }
        __syncthreads();

        #pragma unroll
        for (int kk = 0; kk < KC; kk++) {
            const float* gm = &sG[kk * NT + t0];
            unsigned long long m[4];
            #pragma unroll
            for (int i = 0; i < 4; i++) {
                float mv = sm[kk][r0 + i];
                m[i] = pack2(mv, mv);
            }
            #pragma unroll
            for (int j = 0; j < 10; j++) {
                unsigned long long g = *(const unsigned long long*)(gm + 2 * j);
                #pragma unroll
                for (int i = 0; i < 4; i++) ffma2(acc[i][j], m[i], g);
            }
        }
    }

    const size_t base = ((size_t)ks * BP + (size_t)bb * NPHI + p0) * NT;
    #pragma unroll
    for (int i = 0; i < 4; i++) {
        float* dst = g_Part + base + (size_t)(r0 + i) * NT + t0;
        #pragma unroll
        for (int j = 0; j < 10; j++)
            *(unsigned long long*)(dst + 2 * j) = acc[i][j];
    }
}

__global__ void reduce_kernel(float* __restrict__ out)
{
    int i = blockIdx.x * 256 + threadIdx.x;
    if (i >= BP * NT) return;
    float s = 0.f;
    #pragma unroll
    for (int ksp = 0; ksp < KSPLIT; ksp++)
        s += g_Part[(size_t)ksp * (BP * NT) + i];
    out[i] = s;
}

extern "C" void kernel_launch(void* const* d_in, const int* in_sizes, int n_in,
                              void* d_out, int out_size)
{
    const float* f   = (const float*)d_in[0];   // [16,1,256,256]
    const float* fil = (const float*)d_in[1];   // [512,512]
    const int*  idx0 = (const int*)d_in[2];     // [256]
    const int*  idx1 = (const int*)d_in[3];     // [256]
    float* out = (float*)d_out;                  // [16,1,256,240]

    fft_rows_kernel<<<dim3(NOUT, NB), 256>>>(f);
    fft_cols_kernel<<<dim3(NOUT, NB), 256>>>();
    ggen_kernel<<<(KH + 255) / 256, 256>>>(fil);
    gemm_kernel<<<dim3(BP / BM, KSPLIT), 192>>>(idx0, idx1);
    reduce_kernel<<<(BP * NT + 255) / 256, 256>>>(out);
}

// round 3
// speedup vs baseline: 1.0007x; 1.0007x over previous
#include <cuda_runtime.h>
#include <cuda_bf16.h>

// Problem constants
#define NB   16
#define NIN  256
#define NOUT 512
#define NPHI 256
#define NT   240
#define KH   131584            // 512 * 257 (Hermitian half over axis -1)
#define KSPLIT 8
#define KPB  (KH / KSPLIT)     // 16448
#define KC   16
#define BM   64
#define BP   (NB * NPHI)       // 4096

// ---------------- device scratch (static; no allocation) ----------------
__device__ float2  g_W[NB * NOUT * NOUT];          // full spectrum, 33.5 MB
__device__ float   g_G[(size_t)KH * NT];           // 126 MB
__device__ unsigned g_ab[KH];
__device__ float   g_Part[(size_t)KSPLIT * BP * NT]; // 31.5 MB

// ---------------- 512-point radix-2 DIT FFT in shared memory ----------------
// sign = -1 -> forward DFT (matches numpy/jax fftn). Input loaded bit-reversed,
// output in natural order.
__device__ __forceinline__ void fft512(float2* buf, int tid, float sign)
{
    #pragma unroll
    for (int s = 0; s < 9; s++) {
        int half = 1 << s;
        int pos  = tid & (half - 1);
        int i0   = ((tid >> s) << (s + 1)) + pos;
        int i1   = i0 + half;
        float ang = sign * 3.14159265358979323846f * (float)pos / (float)half;
        float sv, cv;
        sincosf(ang, &sv, &cv);           // NOTE: sin first, cos second
        __syncthreads();
        float2 x0 = buf[i0];
        float2 x1 = buf[i1];
        float tr = x1.x * cv - x1.y * sv; // x1 * e^{i*ang}
        float ti = x1.x * sv + x1.y * cv;
        buf[i0] = make_float2(x0.x + tr, x0.y + ti);
        buf[i1] = make_float2(x0.x - tr, x0.y - ti);
    }
    __syncthreads();
}

// Row FFTs of the zero-padded input: f [16,1,256,256] -> g_W rows
__global__ void fft_rows_kernel(const float* __restrict__ f)
{
    int a  = blockIdx.x;   // output row 0..511 (axis -2 index)
    int bb = blockIdx.y;   // batch
    int tid = threadIdx.x; // 0..255
    float2* wrow = g_W + ((size_t)bb << 18) + ((size_t)a << 9);

    if (a < 128 || a >= 384) {
        for (int i = tid; i < 512; i += 256) wrow[i] = make_float2(0.f, 0.f);
        return;
    }
    __shared__ float2 buf[512];
    const float* frow = f + (size_t)bb * (NIN * NIN) + (size_t)(a - 128) * NIN;
    for (int i = tid; i < 512; i += 256) {
        float v = (i >= 128 && i < 384) ? frow[i - 128] : 0.f;
        buf[__brev((unsigned)i) >> 23] = make_float2(v, 0.f);
    }
    fft512(buf, tid, -1.0f);
    for (int i = tid; i < 512; i += 256) wrow[i] = buf[i];
}

// Column FFTs, in place
__global__ void fft_cols_kernel()
{
    int c  = blockIdx.x;   // column (axis -1 index)
    int bb = blockIdx.y;
    int tid = threadIdx.x;
    float2* base = g_W + ((size_t)bb << 18) + c;
    __shared__ float2 buf[512];
    for (int i = tid; i < 512; i += 256)
        buf[__brev((unsigned)i) >> 23] = base[(size_t)i << 9];
    fft512(buf, tid, -1.0f);
    for (int i = tid; i < 512; i += 256) base[(size_t)i << 9] = buf[i];
}

// G[kh][t] = g_{t+1}(k) * weight / N^2, plus (a,b) table.
// kh = a*257 + b, a in [0,512), b in [0,257)  (half spectrum over axis -1)
__global__ void ggen_kernel(const float* __restrict__ fil)
{
    int kh = blockIdx.x * 256 + threadIdx.x;
    if (kh >= KH) return;
    unsigned a = (unsigned)kh / 257u;
    unsigned b = (unsigned)kh - a * 257u;
    float c2 = 2.0f - 4.0f * fil[a * 512u + b];
    float w  = (b == 0u || b == 256u) ? 1.0f : 2.0f;
    float scale = w * (1.0f / 262144.0f);
    g_ab[kh] = (a << 9) | b;
    float gp = scale;                // g_0 * scale
    float gc = (c2 - 1.0f) * scale;  // g_1 * scale
    float* go = g_G + (size_t)kh * NT;
    #pragma unroll 8
    for (int t = 0; t < NT; t++) {
        go[t] = gc;
        float gn = c2 * gc - gp;
        gp = gc; gc = gn;
    }
}

// packed fp32x2 helpers
__device__ __forceinline__ unsigned long long pack2(float x, float y)
{
    unsigned long long r;
    asm("mov.b64 %0, {%1,%2};" : "=l"(r) : "f"(x), "f"(y));
    return r;
}
__device__ __forceinline__ void ffma2(unsigned long long& d,
                                      unsigned long long a,
                                      unsigned long long b)
{
    asm("fma.rn.f32x2 %0, %1, %2, %0;" : "+l"(d) : "l"(a), "l"(b));
}

// GEMM: Part[ks][bp][t] = sum_{k in split ks} m(bp,k) * G[k][t]
// m(bp,k) = ReW0[b][k]*cos(phi) - ImW0[b][k]*sin(phi),
// phi = 2*pi*((a*idx0[p] + b*idx1[p]) mod 512)/512
__global__ void __launch_bounds__(192, 2)
gemm_kernel(const int* __restrict__ idx0, const int* __restrict__ idx1)
{
    __shared__ float ct[512], st[512];
    __shared__ int   px[BM], py[BM];
    __shared__ float sG[KC * NT];
    __shared__ float sm[KC][BM];
    __shared__ unsigned sv[KC];
    __shared__ float2   sw[KC];

    const int tid = threadIdx.x;          // 0..191
    const int bx  = blockIdx.x;           // 0..63  -> bp tile
    const int ks  = blockIdx.y;           // 0..7   -> k split
    const int bb  = bx >> 2;              // batch (4 tiles of 64 p per batch)
    const int p0  = (bx & 3) * BM;

    for (int i = tid; i < 512; i += 192) {
        float sv_, cv_;
        sincosf(6.283185307179586477f * (float)i * (1.0f / 512.0f), &sv_, &cv_);
        ct[i] = cv_; st[i] = sv_;          // NOTE: sin first, cos second
    }
    for (int i = tid; i < BM; i += 192) { px[i] = idx0[p0 + i]; py[i] = idx1[p0 + i]; }

    // thread tile: 4 rows x 20 t (10 packed pairs)
    const int tg = tid % 12;
    const int rq = tid / 12;      // 0..15
    const int r0 = rq * 4;
    const int t0 = tg * 20;

    unsigned long long acc[4][10];
    #pragma unroll
    for (int i = 0; i < 4; i++)
        #pragma unroll
        for (int j = 0; j < 10; j++) acc[i][j] = 0ull;

    const float2* Wb = g_W + ((size_t)bb << 18);
    const int kbase = ks * KPB;

    for (int kc = 0; kc < KPB; kc += KC) {
        __syncthreads();
        if (tid < KC) {
            unsigned v = g_ab[kbase + kc + tid];
            sv[tid] = v;
            sw[tid] = Wb[v];   // v = (a<<9)|b = a*512+b : direct spectrum offset
        }
        const float* Gsrc = g_G + (size_t)(kbase + kc) * NT;
        for (int i = tid; i < KC * NT; i += 192) sG[i] = Gsrc[i];
        __syncthreads();

        for (int i = tid; i < KC * BM; i += 192) {
            int r = i & (BM - 1);
            int kk = i >> 6;
            unsigned v = sv[kk];
            unsigned ph = ((v >> 9) * (unsigned)px[r] + (v & 511u) * (unsigned)py[r]) & 511u;
            float2 w = sw[kk];
            sm[kk][r] = w.x * ct[ph] - w.y * st[ph];
        }
        __syncthreads();

        #pragma unroll
        for (int kk = 0; kk < KC; kk++) {
            const float* gm = &sG[kk * NT + t0];
            unsigned long long m[4];
            #pragma unroll
            for (int i = 0; i < 4; i++) {
                float mv = sm[kk][r0 + i];
                m[i] = pack2(mv, mv);
            }
            #pragma unroll
            for (int j = 0; j < 10; j++) {
                unsigned long long g = *(const unsigned long long*)(gm + 2 * j);
                #pragma unroll
                for (int i = 0; i < 4; i++) ffma2(acc[i][j], m[i], g);
            }
        }
    }

    const size_t base = ((size_t)ks * BP + (size_t)bb * NPHI + p0) * NT;
    #pragma unroll
    for (int i = 0; i < 4; i++) {
        float* dst = g_Part + base + (size_t)(r0 + i) * NT + t0;
        #pragma unroll
        for (int j = 0; j < 10; j++)
            *(unsigned long long*)(dst + 2 * j) = acc[i][j];
    }
}

__global__ void reduce_kernel(float* __restrict__ out)
{
    int i = blockIdx.x * 256 + threadIdx.x;
    if (i >= BP * NT) return;
    float s = 0.f;
    #pragma unroll
    for (int ksp = 0; ksp < KSPLIT; ksp++)
        s += g_Part[(size_t)ksp * (BP * NT) + i];
    out[i] = s;
}

extern "C" void kernel_launch(void* const* d_in, const int* in_sizes, int n_in,
                              void* d_out, int out_size)
{
    const float* f   = (const float*)d_in[0];   // [16,1,256,256]
    const float* fil = (const float*)d_in[1];   // [512,512]
    const int*  idx0 = (const int*)d_in[2];     // [256]
    const int*  idx1 = (const int*)d_in[3];     // [256]
    float* out = (float*)d_out;                  // [16,1,256,240]

    fft_rows_kernel<<<dim3(NOUT, NB), 256>>>(f);
    fft_cols_kernel<<<dim3(NOUT, NB), 256>>>();
    ggen_kernel<<<(KH + 255) / 256, 256>>>(fil);
    gemm_kernel<<<dim3(BP / BM, KSPLIT), 192>>>(idx0, idx1);
    reduce_kernel<<<(BP * NT + 255) / 256, 256>>>(out);
}

// round 5
// speedup vs baseline: 4.3274x; 4.3244x over previous
#include <cuda_runtime.h>
#include <cuda_bf16.h>
#include <cstdint>

#define NB   16
#define NIN  256
#define NPHI 256
#define NT   240
#define KH   131584            // 512*257 Hermitian half
#define BK   32
#define NCH  (KH / BK)         // 4112
#define KSP  37                // 32*37 = 1184 = 8*148 exact waves
#define NS   3
#define STG_SZ 47104           // A hi/lo 16384 + B hi/lo 30720
#define OFF_AL 8192
#define OFF_BH 16384
#define OFF_BL 31744

// ---------------- device scratch (static; no allocation) ----------------
__device__ float2         g_W[NB * 512 * 512];
__device__ unsigned short g_G1[(size_t)NT * KH];     // G hi bf16, [t][kh]
__device__ unsigned short g_G2[(size_t)NT * KH];     // G lo bf16
__device__ float          g_Part[(size_t)KSP * 4096 * NT];

// ---------------- helpers ----------------
__device__ __forceinline__ uint32_t smem_u32(const void* p){
    uint32_t a; asm("{ .reg .u64 t; cvta.to.shared.u64 t, %1; cvt.u32.u64 %0, t; }":"=r"(a):"l"(p)); return a;
}
__device__ __forceinline__ void cp16(uint32_t dst, const void* src){
    asm volatile("cp.async.cg.shared.global [%0], [%1], 16;" :: "r"(dst), "l"(src) : "memory");
}
__device__ __forceinline__ void sts128(uint32_t a, uint32_t x, uint32_t y, uint32_t z, uint32_t w){
    asm volatile("st.shared.v4.b32 [%0], {%1,%2,%3,%4};" :: "r"(a), "r"(x), "r"(y), "r"(z), "r"(w) : "memory");
}
__device__ __forceinline__ void ldsm4(uint32_t* d, uint32_t a){
    asm volatile("ldmatrix.sync.aligned.m8n8.x4.shared.b16 {%0,%1,%2,%3}, [%4];"
        : "=r"(d[0]), "=r"(d[1]), "=r"(d[2]), "=r"(d[3]) : "r"(a));
}
__device__ __forceinline__ void mma16816(float* c, const uint32_t* a, const uint32_t* b){
    asm volatile("mma.sync.aligned.m16n8k16.row.col.f32.bf16.bf16.f32 "
        "{%0,%1,%2,%3}, {%4,%5,%6,%7}, {%8,%9}, {%0,%1,%2,%3};"
        : "+f"(c[0]), "+f"(c[1]), "+f"(c[2]), "+f"(c[3])
        : "r"(a[0]), "r"(a[1]), "r"(a[2]), "r"(a[3]), "r"(b[0]), "r"(b[1]));
}

// ---------------- 512-pt radix-2 FFT (validated R2) ----------------
__device__ __forceinline__ void fft512(float2* buf, int tid, float sign)
{
    #pragma unroll
    for (int s = 0; s < 9; s++) {
        int half = 1 << s;
        int pos  = tid & (half - 1);
        int i0   = ((tid >> s) << (s + 1)) + pos;
        int i1   = i0 + half;
        float ang = sign * 3.14159265358979323846f * (float)pos / (float)half;
        float sv, cv;
        sincosf(ang, &sv, &cv);
        __syncthreads();
        float2 x0 = buf[i0], x1 = buf[i1];
        float tr = x1.x * cv - x1.y * sv;
        float ti = x1.x * sv + x1.y * cv;
        buf[i0] = make_float2(x0.x + tr, x0.y + ti);
        buf[i1] = make_float2(x0.x - tr, x0.y - ti);
    }
    __syncthreads();
}

__global__ void fft_rows_kernel(const float* __restrict__ f)
{
    int a = blockIdx.x, bb = blockIdx.y, tid = threadIdx.x;
    float2* wrow = g_W + ((size_t)bb << 18) + ((size_t)a << 9);
    if (a < 128 || a >= 384) {
        for (int i = tid; i < 512; i += 256) wrow[i] = make_float2(0.f, 0.f);
        return;
    }
    __shared__ float2 buf[512];
    const float* frow = f + (size_t)bb * (NIN * NIN) + (size_t)(a - 128) * NIN;
    for (int i = tid; i < 512; i += 256) {
        float v = (i >= 128 && i < 384) ? frow[i - 128] : 0.f;
        buf[__brev((unsigned)i) >> 23] = make_float2(v, 0.f);
    }
    fft512(buf, tid, -1.0f);
    for (int i = tid; i < 512; i += 256) wrow[i] = buf[i];
}

__global__ void fft_cols_kernel()
{
    int c = blockIdx.x, bb = blockIdx.y, tid = threadIdx.x;
    float2* base = g_W + ((size_t)bb << 18) + c;
    __shared__ float2 buf[512];
    for (int i = tid; i < 512; i += 256)
        buf[__brev((unsigned)i) >> 23] = base[(size_t)i << 9];
    fft512(buf, tid, -1.0f);
    for (int i = tid; i < 512; i += 256) base[(size_t)i << 9] = buf[i];
}

// ---------------- G tables: bf16 hi/lo split, [t][kh] ----------------
__global__ void ggen_kernel(const float* __restrict__ fil)
{
    int kh = blockIdx.x * 256 + threadIdx.x;
    if (kh >= KH) return;
    unsigned a = (unsigned)kh / 257u;
    unsigned b = (unsigned)kh - a * 257u;
    float c2 = 2.0f - 4.0f * fil[a * 512u + b];
    float w  = (b == 0u || b == 256u) ? 1.0f : 2.0f;
    float scale = w * (1.0f / 262144.0f);
    float gp = scale;                 // g_0 * scale
    float gc = (c2 - 1.0f) * scale;   // g_1 * scale
    #pragma unroll 4
    for (int t = 0; t < NT; t++) {
        unsigned hb = __float_as_uint(gc) & 0xffff0000u;
        float lo = gc - __uint_as_float(hb);
        g_G1[(size_t)t * KH + kh] = (unsigned short)(hb >> 16);
        __nv_bfloat16 lb = __float2bfloat16(lo);
        g_G2[(size_t)t * KH + kh] = *reinterpret_cast<unsigned short*>(&lb);
        float gn = c2 * gc - gp;
        gp = gc; gc = gn;
    }
}

// ---------------- HMMA GEMM ----------------
// C[row][t] = sum_k A[row][k] * G[t][k];  A generated on the fly.
// Block: 512 thr (16 warps = 4m x 4n), M=128 rows, N=240.
__global__ void __launch_bounds__(512, 1)
gemm_kernel(const int* __restrict__ idx0, const int* __restrict__ idx1)
{
    extern __shared__ char smem[];
    const uint32_t sb = smem_u32(smem);
    const int tid = threadIdx.x;
    const int mt = blockIdx.x;       // 0..31
    const int ks = blockIdx.y;       // 0..36
    const int bb = mt >> 1;
    const int c0 = (ks * NCH) / KSP, c1 = ((ks + 1) * NCH) / KSP;

    // ---- A-gen per-thread setup: thread owns (row r, k-group g of 8) ----
    const int r = tid >> 2, g = tid & 3;
    const int p = ((mt & 1) << 7) + r;       // sensor index within batch
    const int x = idx0[p], y = idx1[p];
    const float TH = 6.2831853071795864769e+00f / 512.0f;
    float cy, sy; sincosf((float)(((unsigned)y) & 511u) * TH, &sy, &cy);
    int wd = (x - 256 * y) % 512; if (wd < 0) wd += 512;
    float cw, sw_; sincosf((float)wd * TH, &sw_, &cw);
    const float2* Wb = g_W + ((size_t)bb << 18);

    // ---- warp tiling ----
    const int wid = tid >> 5, lane = tid & 31;
    const int wm = wid & 3, wn = wid >> 2;
    const int mrow0 = wm * 32;
    const int n0 = wn * 64;
    const int npairs = (wn < 3) ? 4 : 3;     // n-tiles(8) pairs: 64,64,64,48
    const int lrowA = (lane & 7) + ((lane >> 3) & 1) * 8;
    const int lchA  = lane >> 4;
    const int lrowB = (lane & 7) + (lane >> 4) * 8;
    const int lchB  = (lane >> 3) & 1;

    float acc[2][8][4];
    #pragma unroll
    for (int s = 0; s < 2; s++)
        #pragma unroll
        for (int t8 = 0; t8 < 8; t8++)
            #pragma unroll
            for (int q = 0; q < 4; q++) acc[s][t8][q] = 0.f;

    // ---------------- produce stage for chunk c ----------------
    auto produce = [&](int c) {
        const uint32_t st = sb + (uint32_t)(c % NS) * STG_SZ;
        const int k0 = c * BK;
        // B hi / lo via cp.async (240 rows x 64B, XOR-swizzled 16B chunks)
        for (int i = tid; i < 960; i += 512) {
            int n = i >> 2, cc = i & 3;
            uint32_t sw4 = (uint32_t)((n >> 1) & 3);
            uint32_t d = st + OFF_BH + (uint32_t)n * 64u + (((uint32_t)cc ^ sw4) << 4);
            cp16(d, g_G1 + (size_t)n * KH + k0 + cc * 8);
        }
        for (int i = tid; i < 960; i += 512) {
            int n = i >> 2, cc = i & 3;
            uint32_t sw4 = (uint32_t)((n >> 1) & 3);
            uint32_t d = st + OFF_BL + (uint32_t)n * 64u + (((uint32_t)cc ^ sw4) << 4);
            cp16(d, g_G2 + (size_t)n * KH + k0 + cc * 8);
        }
        // A: 8 elements kh0..kh0+7, exact integer phase + complex rotation
        {
            int kh0 = k0 + g * 8;
            unsigned a = (unsigned)kh0 / 257u;
            unsigned b = (unsigned)kh0 - a * 257u;
            unsigned off = (a << 9) + b;
            unsigned ph = (a * (unsigned)x + b * (unsigned)y) & 511u;
            float cr, ci; __sincosf((float)ph * TH, &ci, &cr);  // sin->ci, cos->cr
            uint32_t hp[4], lp[4];
            float m0 = 0.f;
            #pragma unroll
            for (int e = 0; e < 8; e++) {
                float2 w = Wb[off];
                float mv = fmaf(w.x, cr, -w.y * ci);
                if ((e & 1) == 0) m0 = mv;
                else {
                    unsigned h0 = __float_as_uint(m0) & 0xffff0000u;
                    unsigned h1 = __float_as_uint(mv) & 0xffff0000u;
                    hp[e >> 1] = __byte_perm(h0, h1, 0x7632);
                    float l0 = m0 - __uint_as_float(h0);
                    float l1 = mv - __uint_as_float(h1);
                    asm("cvt.rn.bf16x2.f32 %0, %1, %2;" : "=r"(lp[e >> 1]) : "f"(l1), "f"(l0));
                }
                bool wrap = (b == 256u);
                float fc = wrap ? cw : cy, fs = wrap ? sw_ : sy;
                float nr = cr * fc - ci * fs;
                float ni = fmaf(cr, fs, ci * fc);
                cr = nr; ci = ni;
                off += wrap ? 256u : 1u;
                b = wrap ? 0u : b + 1u;
            }
            uint32_t sw4 = (uint32_t)((r >> 1) & 3);
            uint32_t da = st + (uint32_t)r * 64u + (((uint32_t)g ^ sw4) << 4);
            sts128(da, hp[0], hp[1], hp[2], hp[3]);
            sts128(da + OFF_AL, lp[0], lp[1], lp[2], lp[3]);
        }
        asm volatile("cp.async.commit_group;" ::: "memory");
    };

    // ---------------- consume chunk c ----------------
    auto consume = [&](int c) {
        const uint32_t st = sb + (uint32_t)(c % NS) * STG_SZ;
        #pragma unroll
        for (int ks2 = 0; ks2 < 2; ks2++) {
            uint32_t Ah[2][4], Al[2][4];
            #pragma unroll
            for (int s = 0; s < 2; s++) {
                int row = mrow0 + s * 16 + lrowA;
                uint32_t sw4 = (uint32_t)((row >> 1) & 3);
                uint32_t a1 = st + (uint32_t)row * 64u + ((((uint32_t)(ks2 * 2 + lchA)) ^ sw4) << 4);
                ldsm4(Ah[s], a1);
                ldsm4(Al[s], a1 + OFF_AL);
            }
            #pragma unroll
            for (int jp = 0; jp < 4; jp++) {
                if (jp < npairs) {
                    int nr_ = n0 + jp * 16 + lrowB;
                    uint32_t sw4 = (uint32_t)((nr_ >> 1) & 3);
                    uint32_t ba = st + OFF_BH + (uint32_t)nr_ * 64u +
                                  ((((uint32_t)(ks2 * 2 + lchB)) ^ sw4) << 4);
                    uint32_t Bf[4];
                    ldsm4(Bf, ba);                       // B hi
                    #pragma unroll
                    for (int s = 0; s < 2; s++) {
                        mma16816(acc[s][2 * jp],     Ah[s], Bf);
                        mma16816(acc[s][2 * jp + 1], Ah[s], Bf + 2);
                        mma16816(acc[s][2 * jp],     Al[s], Bf);
                        mma16816(acc[s][2 * jp + 1], Al[s], Bf + 2);
                    }
                    ldsm4(Bf, ba + (OFF_BL - OFF_BH));   // B lo
                    #pragma unroll
                    for (int s = 0; s < 2; s++) {
                        mma16816(acc[s][2 * jp],     Ah[s], Bf);
                        mma16816(acc[s][2 * jp + 1], Ah[s], Bf + 2);
                    }
                }
            }
        }
    };

    // ---------------- pipeline ----------------
    produce(c0);
    produce(c0 + 1);
    for (int c = c0; c < c1; c++) {
        asm volatile("cp.async.wait_group 1;" ::: "memory");
        __syncthreads();
        consume(c);
        if (c + 2 < c1) produce(c + 2);
        else asm volatile("cp.async.commit_group;" ::: "memory");
    }

    // ---------------- epilogue: write partials ----------------
    const int gq = lane >> 2, tg = lane & 3;
    #pragma unroll
    for (int s = 0; s < 2; s++) {
        const int rbase = mt * 128 + mrow0 + s * 16 + gq;
        #pragma unroll
        for (int t8 = 0; t8 < 8; t8++) {
            if (t8 < npairs * 2) {
                const int tt = n0 + t8 * 8 + tg * 2;
                float* d0 = g_Part + ((size_t)ks * 4096 + rbase) * NT + tt;
                *(float2*)d0 = make_float2(acc[s][t8][0], acc[s][t8][1]);
                float* d1 = d0 + 8 * NT;
                *(float2*)d1 = make_float2(acc[s][t8][2], acc[s][t8][3]);
            }
        }
    }
}

// ---------------- reduce over k-splits ----------------
__global__ void reduce_kernel(float* __restrict__ out)
{
    int i = blockIdx.x * 256 + threadIdx.x;   // i = row*240 + t
    if (i >= 4096 * NT) return;
    float s = 0.f;
    #pragma unroll
    for (int k = 0; k < KSP; k++) s += g_Part[(size_t)k * (4096 * NT) + i];
    out[i] = s;
}

extern "C" void kernel_launch(void* const* d_in, const int* in_sizes, int n_in,
                              void* d_out, int out_size)
{
    const float* f   = (const float*)d_in[0];
    const float* fil = (const float*)d_in[1];
    const int*  idx0 = (const int*)d_in[2];
    const int*  idx1 = (const int*)d_in[3];
    float* out = (float*)d_out;

    cudaFuncSetAttribute(gemm_kernel, cudaFuncAttributeMaxDynamicSharedMemorySize, NS * STG_SZ);

    fft_rows_kernel<<<dim3(512, NB), 256>>>(f);
    fft_cols_kernel<<<dim3(512, NB), 256>>>();
    ggen_kernel<<<(KH + 255) / 256, 256>>>(fil);
    gemm_kernel<<<dim3(32, KSP), 512, NS * STG_SZ>>>(idx0, idx1);
    reduce_kernel<<<(4096 * NT + 255) / 256, 256>>>(out);
}

// round 6
// speedup vs baseline: 4.8059x; 1.1106x over previous
#include <cuda_runtime.h>
#include <cuda_bf16.h>
#include <cstdint>

#define NB   16
#define NIN  256
#define NPHI 256
#define NT   240
#define KH   131584            // 512*257 Hermitian half
#define BK   32
#define NCH  (KH / BK)         // 4112
#define KSP  37                // 32*37 = 1184 = 8*148 exact waves
#define NS   3
#define STG_SZ 47104           // A hi/lo 16384 + B hi/lo 30720
#define OFF_AL 8192
#define OFF_BH 16384
#define OFF_BL 31744

// ---------------- device scratch (static; no allocation) ----------------
__device__ float2         g_W[NB * 512 * 512];
__device__ unsigned short g_G1[(size_t)NT * KH];     // G hi bf16, [t][kh]
__device__ unsigned short g_G2[(size_t)NT * KH];     // G lo bf16
__device__ float          g_Part[(size_t)KSP * 4096 * NT];

// ---------------- helpers ----------------
__device__ __forceinline__ uint32_t smem_u32(const void* p){
    uint32_t a; asm("{ .reg .u64 t; cvta.to.shared.u64 t, %1; cvt.u32.u64 %0, t; }":"=r"(a):"l"(p)); return a;
}
__device__ __forceinline__ void cp16(uint32_t dst, const void* src){
    asm volatile("cp.async.cg.shared.global [%0], [%1], 16;" :: "r"(dst), "l"(src) : "memory");
}
__device__ __forceinline__ void sts128(uint32_t a, uint32_t x, uint32_t y, uint32_t z, uint32_t w){
    asm volatile("st.shared.v4.b32 [%0], {%1,%2,%3,%4};" :: "r"(a), "r"(x), "r"(y), "r"(z), "r"(w) : "memory");
}
__device__ __forceinline__ void ldsm4(uint32_t* d, uint32_t a){
    asm volatile("ldmatrix.sync.aligned.m8n8.x4.shared.b16 {%0,%1,%2,%3}, [%4];"
        : "=r"(d[0]), "=r"(d[1]), "=r"(d[2]), "=r"(d[3]) : "r"(a));
}
__device__ __forceinline__ void mma16816(float* c, const uint32_t* a, const uint32_t* b){
    asm volatile("mma.sync.aligned.m16n8k16.row.col.f32.bf16.bf16.f32 "
        "{%0,%1,%2,%3}, {%4,%5,%6,%7}, {%8,%9}, {%0,%1,%2,%3};"
        : "+f"(c[0]), "+f"(c[1]), "+f"(c[2]), "+f"(c[3])
        : "r"(a[0]), "r"(a[1]), "r"(a[2]), "r"(a[3]), "r"(b[0]), "r"(b[1]));
}
__device__ __forceinline__ void bar_sync(int id){
    asm volatile("bar.sync %0, 512;" :: "r"(id) : "memory");
}
__device__ __forceinline__ void bar_arrive(int id){
    asm volatile("bar.arrive %0, 512;" :: "r"(id) : "memory");
}

// ---------------- 512-pt radix-2 FFT (validated) ----------------
__device__ __forceinline__ void fft512(float2* buf, int tid, float sign)
{
    #pragma unroll
    for (int s = 0; s < 9; s++) {
        int half = 1 << s;
        int pos  = tid & (half - 1);
        int i0   = ((tid >> s) << (s + 1)) + pos;
        int i1   = i0 + half;
        float ang = sign * 3.14159265358979323846f * (float)pos / (float)half;
        float sv, cv;
        sincosf(ang, &sv, &cv);
        __syncthreads();
        float2 x0 = buf[i0], x1 = buf[i1];
        float tr = x1.x * cv - x1.y * sv;
        float ti = x1.x * sv + x1.y * cv;
        buf[i0] = make_float2(x0.x + tr, x0.y + ti);
        buf[i1] = make_float2(x0.x - tr, x0.y - ti);
    }
    __syncthreads();
}

__global__ void fft_rows_kernel(const float* __restrict__ f)
{
    int a = blockIdx.x, bb = blockIdx.y, tid = threadIdx.x;
    float2* wrow = g_W + ((size_t)bb << 18) + ((size_t)a << 9);
    if (a < 128 || a >= 384) {
        for (int i = tid; i < 512; i += 256) wrow[i] = make_float2(0.f, 0.f);
        return;
    }
    __shared__ float2 buf[512];
    const float* frow = f + (size_t)bb * (NIN * NIN) + (size_t)(a - 128) * NIN;
    for (int i = tid; i < 512; i += 256) {
        float v = (i >= 128 && i < 384) ? frow[i - 128] : 0.f;
        buf[__brev((unsigned)i) >> 23] = make_float2(v, 0.f);
    }
    fft512(buf, tid, -1.0f);
    for (int i = tid; i < 512; i += 256) wrow[i] = buf[i];
}

__global__ void fft_cols_kernel()
{
    int c = blockIdx.x, bb = blockIdx.y, tid = threadIdx.x;
    float2* base = g_W + ((size_t)bb << 18) + c;
    __shared__ float2 buf[512];
    for (int i = tid; i < 512; i += 256)
        buf[__brev((unsigned)i) >> 23] = base[(size_t)i << 9];
    fft512(buf, tid, -1.0f);
    for (int i = tid; i < 512; i += 256) base[(size_t)i << 9] = buf[i];
}

// ---------------- G tables: bf16 hi/lo split, [t][kh] ----------------
__global__ void ggen_kernel(const float* __restrict__ fil)
{
    int kh = blockIdx.x * 256 + threadIdx.x;
    if (kh >= KH) return;
    unsigned a = (unsigned)kh / 257u;
    unsigned b = (unsigned)kh - a * 257u;
    float c2 = 2.0f - 4.0f * fil[a * 512u + b];
    float w  = (b == 0u || b == 256u) ? 1.0f : 2.0f;
    float scale = w * (1.0f / 262144.0f);
    float gp = scale;
    float gc = (c2 - 1.0f) * scale;
    #pragma unroll 4
    for (int t = 0; t < NT; t++) {
        unsigned hb = __float_as_uint(gc) & 0xffff0000u;
        float lo = gc - __uint_as_float(hb);
        g_G1[(size_t)t * KH + kh] = (unsigned short)(hb >> 16);
        __nv_bfloat16 lb = __float2bfloat16(lo);
        g_G2[(size_t)t * KH + kh] = *reinterpret_cast<unsigned short*>(&lb);
        float gn = c2 * gc - gp;
        gp = gc; gc = gn;
    }
}

// ---------------- warp-specialized HMMA GEMM ----------------
// 512 thr: warps 0-11 consumers (4m x 3n, n=80 each), warps 12-15 producers.
// Named barriers: full[s]=1+s (producer arrive, consumer sync),
//                 empty[s]=4+s (consumer arrive, producer sync).
__global__ void __launch_bounds__(512, 1)
gemm_kernel(const int* __restrict__ idx0, const int* __restrict__ idx1)
{
    extern __shared__ char smem[];
    const uint32_t sb = smem_u32(smem);
    const int tid = threadIdx.x;
    const int wid = tid >> 5, lane = tid & 31;
    const int mt = blockIdx.x;       // 0..31
    const int ks = blockIdx.y;       // 0..36
    const int bb = mt >> 1;
    const int c0 = (ks * NCH) / KSP, c1 = ((ks + 1) * NCH) / KSP;

    if (wid >= 12) {
        // ================= PRODUCER (4 warps, 128 threads) =================
        const int r = tid - 384;                 // row 0..127
        const int p = ((mt & 1) << 7) + r;
        const int x = idx0[p], y = idx1[p];
        const float TH = 6.2831853071795864769e+00f / 512.0f;
        float cy, sy; sincosf((float)(((unsigned)y) & 511u) * TH, &sy, &cy);
        int wd = (x - 256 * y) % 512; if (wd < 0) wd += 512;
        float cw, sw_; sincosf((float)wd * TH, &sw_, &cw);
        const float2* Wb = g_W + ((size_t)bb << 18);
        const uint32_t rsw = ((uint32_t)r >> 1) & 3u;

        for (int c = c0; c < c1; c++) {
            const int s = c % 3;
            if (c >= c0 + NS) bar_sync(4 + s);
            const uint32_t st = sb + (uint32_t)s * STG_SZ;
            const int k0 = c * BK;

            // B hi/lo via cp.async: 1920 16B chunks over 128 threads
            #pragma unroll
            for (int ii = 0; ii < 15; ii++) {
                int i = r + ii * 128;
                int half = i >= 960;
                int j = i - (half ? 960 : 0);
                int n = j >> 2, cc = j & 3;
                uint32_t d = st + (half ? OFF_BL : OFF_BH) + (uint32_t)n * 64u
                           + ((((uint32_t)cc) ^ (((uint32_t)n >> 1) & 3u)) << 4);
                const unsigned short* src = (half ? g_G2 : g_G1) + (size_t)n * KH + k0 + cc * 8;
                cp16(d, src);
            }
            asm volatile("cp.async.commit_group;" ::: "memory");

            // A-gen: 32 k-elems for row r (exact int phase + rotation)
            {
                unsigned a0 = (unsigned)k0 / 257u;
                unsigned b  = (unsigned)k0 - a0 * 257u;
                unsigned off = (a0 << 9) + b;
                unsigned ph = (a0 * (unsigned)x + b * (unsigned)y) & 511u;
                float cr, ci; __sincosf((float)ph * TH, &ci, &cr);
                #pragma unroll
                for (int q = 0; q < 4; q++) {
                    uint32_t hp[4], lp[4];
                    float m0 = 0.f;
                    #pragma unroll
                    for (int e = 0; e < 8; e++) {
                        float2 w = Wb[off];
                        float mv = fmaf(w.x, cr, -w.y * ci);
                        if ((e & 1) == 0) m0 = mv;
                        else {
                            unsigned h0 = __float_as_uint(m0) & 0xffff0000u;
                            unsigned h1 = __float_as_uint(mv) & 0xffff0000u;
                            hp[e >> 1] = __byte_perm(h0, h1, 0x7632);
                            float l0 = m0 - __uint_as_float(h0);
                            float l1 = mv - __uint_as_float(h1);
                            asm("cvt.rn.bf16x2.f32 %0, %1, %2;" : "=r"(lp[e >> 1]) : "f"(l1), "f"(l0));
                        }
                        bool wrap = (b == 256u);
                        float fc = wrap ? cw : cy, fs = wrap ? sw_ : sy;
                        float nr = cr * fc - ci * fs;
                        float ni = fmaf(cr, fs, ci * fc);
                        cr = nr; ci = ni;
                        off += wrap ? 256u : 1u;
                        b = wrap ? 0u : b + 1u;
                    }
                    uint32_t da = st + (uint32_t)r * 64u + ((((uint32_t)q) ^ rsw) << 4);
                    sts128(da, hp[0], hp[1], hp[2], hp[3]);
                    sts128(da + OFF_AL, lp[0], lp[1], lp[2], lp[3]);
                }
            }
            asm volatile("cp.async.wait_group 0;" ::: "memory");
            bar_arrive(1 + s);
        }
    } else {
        // ================= CONSUMER (12 warps = 4m x 3n) =================
        const int wm = wid & 3, wn = wid >> 2;       // wn 0..2
        const int mrow0 = wm * 32;
        const int n0 = wn * 80;                       // 3 x 80 = 240
        const int lrowA = (lane & 7) + ((lane >> 3) & 1) * 8;
        const int lchA  = lane >> 4;
        const int lrowB = (lane & 7) + (lane >> 4) * 8;
        const int lchB  = (lane >> 3) & 1;

        float acc[2][10][4];
        #pragma unroll
        for (int s = 0; s < 2; s++)
            #pragma unroll
            for (int t8 = 0; t8 < 10; t8++)
                #pragma unroll
                for (int q = 0; q < 4; q++) acc[s][t8][q] = 0.f;

        for (int c = c0; c < c1; c++) {
            const int s3 = c % 3;
            bar_sync(1 + s3);
            const uint32_t st = sb + (uint32_t)s3 * STG_SZ;
            #pragma unroll
            for (int ks2 = 0; ks2 < 2; ks2++) {
                uint32_t Ah[2][4], Al[2][4];
                #pragma unroll
                for (int s = 0; s < 2; s++) {
                    int row = mrow0 + s * 16 + lrowA;
                    uint32_t sw4 = (uint32_t)((row >> 1) & 3);
                    uint32_t a1 = st + (uint32_t)row * 64u
                                + ((((uint32_t)(ks2 * 2 + lchA)) ^ sw4) << 4);
                    ldsm4(Ah[s], a1);
                    ldsm4(Al[s], a1 + OFF_AL);
                }
                #pragma unroll
                for (int jp = 0; jp < 5; jp++) {
                    int nr_ = n0 + jp * 16 + lrowB;
                    uint32_t sw4 = (uint32_t)((nr_ >> 1) & 3);
                    uint32_t ba = st + OFF_BH + (uint32_t)nr_ * 64u
                                + ((((uint32_t)(ks2 * 2 + lchB)) ^ sw4) << 4);
                    uint32_t Bf[4];
                    ldsm4(Bf, ba);                       // B hi
                    #pragma unroll
                    for (int s = 0; s < 2; s++) {
                        mma16816(acc[s][2 * jp],     Ah[s], Bf);
                        mma16816(acc[s][2 * jp + 1], Ah[s], Bf + 2);
                        mma16816(acc[s][2 * jp],     Al[s], Bf);
                        mma16816(acc[s][2 * jp + 1], Al[s], Bf + 2);
                    }
                    ldsm4(Bf, ba + (OFF_BL - OFF_BH));   // B lo
                    #pragma unroll
                    for (int s = 0; s < 2; s++) {
                        mma16816(acc[s][2 * jp],     Ah[s], Bf);
                        mma16816(acc[s][2 * jp + 1], Ah[s], Bf + 2);
                    }
                }
            }
            bar_arrive(4 + s3);
        }

        // epilogue: write partials
        const int gq = lane >> 2, tg = lane & 3;
        #pragma unroll
        for (int s = 0; s < 2; s++) {
            const int rbase = mt * 128 + mrow0 + s * 16 + gq;
            #pragma unroll
            for (int t8 = 0; t8 < 10; t8++) {
                const int tt = n0 + t8 * 8 + tg * 2;
                float* d0 = g_Part + ((size_t)ks * 4096 + rbase) * NT + tt;
                *(float2*)d0 = make_float2(acc[s][t8][0], acc[s][t8][1]);
                float* d1 = d0 + 8 * NT;
                *(float2*)d1 = make_float2(acc[s][t8][2], acc[s][t8][3]);
            }
        }
    }
}

// ---------------- reduce over k-splits ----------------
__global__ void reduce_kernel(float* __restrict__ out)
{
    int i = blockIdx.x * 256 + threadIdx.x;   // i = row*240 + t
    if (i >= 4096 * NT) return;
    float s = 0.f;
    #pragma unroll
    for (int k = 0; k < KSP; k++) s += g_Part[(size_t)k * (4096 * NT) + i];
    out[i] = s;
}

extern "C" void kernel_launch(void* const* d_in, const int* in_sizes, int n_in,
                              void* d_out, int out_size)
{
    const float* f   = (const float*)d_in[0];
    const float* fil = (const float*)d_in[1];
    const int*  idx0 = (const int*)d_in[2];
    const int*  idx1 = (const int*)d_in[3];
    float* out = (float*)d_out;

    cudaFuncSetAttribute(gemm_kernel, cudaFuncAttributeMaxDynamicSharedMemorySize, NS * STG_SZ);

    fft_rows_kernel<<<dim3(512, NB), 256>>>(f);
    fft_cols_kernel<<<dim3(512, NB), 256>>>();
    ggen_kernel<<<(KH + 255) / 256, 256>>>(fil);
    gemm_kernel<<<dim3(32, KSP), 512, NS * STG_SZ>>>(idx0, idx1);
    reduce_kernel<<<(4096 * NT + 255) / 256, 256>>>(out);
}